// round 4
// baseline (speedup 1.0000x reference)
#include <cuda_runtime.h>
#include <math.h>

// ---------------------------------------------------------------------------
// Problem dimensions (fixed by the reference setup)
// ---------------------------------------------------------------------------
#define B_SZ   8
#define N_PTS  500
#define M_HYP  144
#define M16    16
#define PS     8           // point slices per (b,m) for the residual kernel

#define C0 128
#define H0 48
#define W0 64
#define C1 64
#define H1 96
#define W1 128
#define C2 32
#define H2 192
#define W2 256

// ---------------------------------------------------------------------------
// Scratch (__device__ globals — no allocation allowed)
// ---------------------------------------------------------------------------
__device__ float g_D0[(size_t)B_SZ * H0 * W0 * C0];   // q0-r0, channel-last
__device__ float g_D1[(size_t)B_SZ * H1 * W1 * C1];
__device__ float g_D2[(size_t)B_SZ * H2 * W2 * C2];
__device__ float g_Tcur[B_SZ * M_HYP * 16];
__device__ float g_resacc[PS * B_SZ * M16];
__device__ float g_costs[B_SZ * M_HYP];

// ---------------------------------------------------------------------------
// Threefry-2x32 (exactly JAX's 20-round schedule; KAT-verified)
// ---------------------------------------------------------------------------
__host__ __device__ __forceinline__ void threefry2x32(
    unsigned k0, unsigned k1, unsigned x0, unsigned x1,
    unsigned* o0, unsigned* o1)
{
  unsigned ks2 = k0 ^ k1 ^ 0x1BD11BDAu;
#define TFR(r) { x0 += x1; x1 = (x1 << (r)) | (x1 >> (32 - (r))); x1 ^= x0; }
  x0 += k0;  x1 += k1;
  TFR(13) TFR(15) TFR(26) TFR(6)
  x0 += k1;  x1 += ks2 + 1u;
  TFR(17) TFR(29) TFR(16) TFR(24)
  x0 += ks2; x1 += k0 + 2u;
  TFR(13) TFR(15) TFR(26) TFR(6)
  x0 += k0;  x1 += k1 + 3u;
  TFR(17) TFR(29) TFR(16) TFR(24)
  x0 += k1;  x1 += ks2 + 4u;
  TFR(13) TFR(15) TFR(26) TFR(6)
  x0 += ks2; x1 += k0 + 5u;
#undef TFR
  *o0 = x0; *o1 = x1;
}

// Giles/XLA erfinv (same coefficients as XLA ErfInv32)
__device__ __forceinline__ float erfinv_f(float x)
{
  float w = -log1pf(-x * x);
  float p;
  if (w < 5.0f) {
    w = w - 2.5f;
    p = 2.81022636e-08f;
    p = fmaf(p, w, 3.43273939e-07f);
    p = fmaf(p, w, -3.5233877e-06f);
    p = fmaf(p, w, -4.39150654e-06f);
    p = fmaf(p, w, 0.00021858087f);
    p = fmaf(p, w, -0.00125372503f);
    p = fmaf(p, w, -0.00417768164f);
    p = fmaf(p, w, 0.246640727f);
    p = fmaf(p, w, 1.50140941f);
  } else {
    w = sqrtf(w) - 3.0f;
    p = -0.000200214257f;
    p = fmaf(p, w, 0.000100950558f);
    p = fmaf(p, w, 0.00134934322f);
    p = fmaf(p, w, -0.00367342844f);
    p = fmaf(p, w, 0.00573950773f);
    p = fmaf(p, w, -0.0076224613f);
    p = fmaf(p, w, 0.00943887047f);
    p = fmaf(p, w, 1.00167406f);
    p = fmaf(p, w, 2.83297682f);
  }
  return p * x;
}

// JAX random.normal from raw 32 bits: u in [0,1), v = max(lo, u*2 + lo), sqrt2*erfinv(v)
__device__ __forceinline__ float bits_to_normal(unsigned bits)
{
  float u = __uint_as_float((bits >> 9) | 0x3f800000u) - 1.0f;
  const float lo = -0.99999994f;               // nextafter(-1,0) in f32
  float v = fmaxf(lo, u * 2.0f + lo);          // (maxval-minval) rounds to 2.0f
  return 1.41421356237f * erfinv_f(v);
}

// PARTITIONABLE threefry (modern JAX default): element j has 64-bit counter j
// -> (y0,y1) = threefry(key; hi=0, lo=j); 32-bit draw = y0 ^ y1.
__device__ __forceinline__ float jax_normal_elem(unsigned k0, unsigned k1, unsigned j)
{
  unsigned y0, y1;
  threefry2x32(k0, k1, 0u, j, &y0, &y1);
  return bits_to_normal(y0 ^ y1);
}

// ---------------------------------------------------------------------------
// se3_exp (matches reference element-by-element)
// ---------------------------------------------------------------------------
__device__ __forceinline__ void mat3mul(const float* A, const float* Bm, float* Cm)
{
#pragma unroll
  for (int i = 0; i < 3; i++)
#pragma unroll
    for (int j = 0; j < 3; j++)
      Cm[i * 3 + j] = A[i * 3 + 0] * Bm[0 * 3 + j] + A[i * 3 + 1] * Bm[1 * 3 + j] + A[i * 3 + 2] * Bm[2 * 3 + j];
}

__device__ void se3_exp6(const float xi[6], float T[16])
{
  float tx = xi[0], ty = xi[1], tz = xi[2];
  float wx = xi[3], wy = xi[4], wz = xi[5];
  float theta = fmaxf(sqrtf(wx * wx + wy * wy + wz * wz), 1e-8f);
  float kx = wx / theta, ky = wy / theta, kz = wz / theta;
  float K[9] = { 0.f, -kz, ky,  kz, 0.f, -kx,  -ky, kx, 0.f };
  float KK[9];
  mat3mul(K, K, KK);
  float st = sinf(theta);
  float ct = 1.0f - cosf(theta);
  float a  = ct / theta;
  float bb = 1.0f - st / theta;
  float R[9], V[9];
#pragma unroll
  for (int i = 0; i < 9; i++) {
    float e = (i == 0 || i == 4 || i == 8) ? 1.0f : 0.0f;
    R[i] = e + st * K[i] + ct * KK[i];
    V[i] = e + a  * K[i] + bb * KK[i];
  }
  float tox = V[0] * tx + V[1] * ty + V[2] * tz;
  float toy = V[3] * tx + V[4] * ty + V[5] * tz;
  float toz = V[6] * tx + V[7] * ty + V[8] * tz;
  T[0] = R[0]; T[1] = R[1]; T[2]  = R[2]; T[3]  = tox;
  T[4] = R[3]; T[5] = R[4]; T[6]  = R[5]; T[7]  = toy;
  T[8] = R[6]; T[9] = R[7]; T[10] = R[8]; T[11] = toz;
  T[12] = 0.f; T[13] = 0.f; T[14] = 0.f; T[15] = 1.f;
}

// ---------------------------------------------------------------------------
// Kernel: D = q - r, transposed (B,C,HW) -> (B,HW,C)
// ---------------------------------------------------------------------------
__global__ void diff_transpose(const float* __restrict__ q, const float* __restrict__ r,
                               float* __restrict__ Dt, int C, int HW)
{
  __shared__ float tile[32][33];
  int b   = blockIdx.z;
  int hw0 = blockIdx.x * 32;
  int c0  = blockIdx.y * 32;
  const float* qb = q + (size_t)b * C * HW;
  const float* rb = r + (size_t)b * C * HW;
  float* Db = Dt + (size_t)b * HW * C;
  int tx = threadIdx.x, ty = threadIdx.y;
#pragma unroll
  for (int i = ty; i < 32; i += 8) {
    int c = c0 + i, hw = hw0 + tx;
    tile[i][tx] = qb[(size_t)c * HW + hw] - rb[(size_t)c * HW + hw];
  }
  __syncthreads();
#pragma unroll
  for (int i = ty; i < 32; i += 8) {
    int hw = hw0 + i, c = c0 + tx;
    Db[(size_t)hw * C + c] = tile[tx][i];
  }
}

// ---------------------------------------------------------------------------
// Kernel: generate 144 hypotheses, T_cur[b,m] = se3_exp(xi_m) @ T_pred[b]
// ---------------------------------------------------------------------------
__global__ void hyp_kernel(const float* __restrict__ Tpred, unsigned k0, unsigned k1)
{
  int m = threadIdx.x;
  if (m >= M_HYP) return;
  float xi[6];
#pragma unroll
  for (int k = 0; k < 3; k++)
    xi[k] = jax_normal_elem(k0, k1, (unsigned)(m * 3 + k));   // (144,3) flattened
  int pi = m / 12, yj = m % 12;
  const float D2R = (float)(3.14159265358979323846 / 180.0);
  xi[3] = 0.0f;
  xi[4] = (-11.0f + 2.0f * (float)pi) * D2R;
  xi[5] = (-11.0f + 2.0f * (float)yj) * D2R;
  float dT[16];
  se3_exp6(xi, dT);
#pragma unroll 1
  for (int b = 0; b < B_SZ; b++) {
    const float* P = Tpred + b * 16;
    float* O = g_Tcur + (size_t)(b * M_HYP + m) * 16;
#pragma unroll
    for (int i = 0; i < 4; i++)
#pragma unroll
      for (int j = 0; j < 4; j++)
        O[i * 4 + j] = dT[i * 4 + 0] * P[0 * 4 + j] + dT[i * 4 + 1] * P[1 * 4 + j]
                     + dT[i * 4 + 2] * P[2 * 4 + j] + dT[i * 4 + 3] * P[3 * 4 + j];
  }
}

// ---------------------------------------------------------------------------
// Kernel: residuals.  grid = B*16*PS blocks, 128 threads.
// Each warp handles points n = sliceBase+wid, +4, ...; lanes cover channels.
// ---------------------------------------------------------------------------
template <int VEC>
__global__ __launch_bounds__(128) void residual_kernel(
    const float* __restrict__ Dt, const float* __restrict__ Umap,
    const float* __restrict__ geo, const float* __restrict__ Kin,
    int C, int H, int W, float scale)
{
  int bm    = blockIdx.x >> 3;     // / PS
  int slice = blockIdx.x & 7;
  int b = bm >> 4, m = bm & 15;
  int lane = threadIdx.x & 31, wid = threadIdx.x >> 5;

  const float* T = g_Tcur + (size_t)(b * M_HYP + m) * 16;
  float T00 = T[0], T01 = T[1], T02 = T[2],  T03 = T[3];
  float T10 = T[4], T11 = T[5], T12 = T[6],  T13 = T[7];
  float T20 = T[8], T21 = T[9], T22 = T[10], T23 = T[11];
  float fx = __ldg(Kin + b * 9 + 0) * scale, cx = __ldg(Kin + b * 9 + 2) * scale;
  float fy = __ldg(Kin + b * 9 + 4) * scale, cy = __ldg(Kin + b * 9 + 5) * scale;
  const float* Db = Dt + (size_t)b * H * W * C;
  const float* Ub = Umap + (size_t)b * H * W;
  const float* G  = geo + (size_t)b * N_PTS * 3;

  float Wm1 = (float)(W - 1), Hm1 = (float)(H - 1);
  float wacc = 0.0f;
  int nbeg = slice * 63 + wid;
  int nend = min(N_PTS, slice * 63 + 63);
  for (int n = nbeg; n < nend; n += 4) {
    float X = __ldg(G + n * 3 + 0);
    float Y = __ldg(G + n * 3 + 1);
    float Z = __ldg(G + n * 3 + 2);
    float px = T00 * X + T01 * Y + T02 * Z + T03;
    float py = T10 * X + T11 * Y + T12 * Z + T13;
    float pz = T20 * X + T21 * Y + T22 * Z + T23;
    float z  = fmaxf(pz, 1e-6f);
    float u  = fx * (px / z) + cx;
    float v  = fy * (py / z) + cy;
    float gx = 2.0f * u / Wm1 - 1.0f;
    float gy = 2.0f * v / Hm1 - 1.0f;
    float xs = fminf(fmaxf(((gx + 1.0f) * (float)W - 1.0f) * 0.5f, 0.0f), Wm1);
    float ys = fminf(fmaxf(((gy + 1.0f) * (float)H - 1.0f) * 0.5f, 0.0f), Hm1);
    float x0f = floorf(xs), y0f = floorf(ys);
    float x1f = fminf(x0f + 1.0f, Wm1), y1f = fminf(y0f + 1.0f, Hm1);
    float wx = xs - x0f, wy = ys - y0f;
    int x0 = (int)x0f, x1 = (int)x1f, y0 = (int)y0f, y1 = (int)y1f;
    float w00 = (1.0f - wx) * (1.0f - wy), w01 = wx * (1.0f - wy);
    float w10 = (1.0f - wx) * wy,          w11 = wx * wy;
    int r0 = y0 * W, r1 = y1 * W;

    float ssum = 0.0f;
    if constexpr (VEC == 4) {
      const float4* p00 = (const float4*)(Db + (size_t)(r0 + x0) * C) + lane;
      const float4* p01 = (const float4*)(Db + (size_t)(r0 + x1) * C) + lane;
      const float4* p10 = (const float4*)(Db + (size_t)(r1 + x0) * C) + lane;
      const float4* p11 = (const float4*)(Db + (size_t)(r1 + x1) * C) + lane;
      float4 a = __ldg(p00), bq = __ldg(p01), c = __ldg(p10), d = __ldg(p11);
      float d0 = w00 * a.x + w01 * bq.x + w10 * c.x + w11 * d.x;
      float d1 = w00 * a.y + w01 * bq.y + w10 * c.y + w11 * d.y;
      float d2 = w00 * a.z + w01 * bq.z + w10 * c.z + w11 * d.z;
      float d3 = w00 * a.w + w01 * bq.w + w10 * c.w + w11 * d.w;
      ssum = d0 * d0 + d1 * d1 + d2 * d2 + d3 * d3;
    } else if constexpr (VEC == 2) {
      const float2* p00 = (const float2*)(Db + (size_t)(r0 + x0) * C) + lane;
      const float2* p01 = (const float2*)(Db + (size_t)(r0 + x1) * C) + lane;
      const float2* p10 = (const float2*)(Db + (size_t)(r1 + x0) * C) + lane;
      const float2* p11 = (const float2*)(Db + (size_t)(r1 + x1) * C) + lane;
      float2 a = __ldg(p00), bq = __ldg(p01), c = __ldg(p10), d = __ldg(p11);
      float d0 = w00 * a.x + w01 * bq.x + w10 * c.x + w11 * d.x;
      float d1 = w00 * a.y + w01 * bq.y + w10 * c.y + w11 * d.y;
      ssum = d0 * d0 + d1 * d1;
    } else {
      float a  = __ldg(Db + (size_t)(r0 + x0) * C + lane);
      float bq = __ldg(Db + (size_t)(r0 + x1) * C + lane);
      float c  = __ldg(Db + (size_t)(r1 + x0) * C + lane);
      float d  = __ldg(Db + (size_t)(r1 + x1) * C + lane);
      float d0 = w00 * a + w01 * bq + w10 * c + w11 * d;
      ssum = d0 * d0;
    }
#pragma unroll
    for (int o = 16; o; o >>= 1) ssum += __shfl_xor_sync(0xffffffffu, ssum, o);
    float us = w00 * __ldg(Ub + r0 + x0) + w01 * __ldg(Ub + r0 + x1)
             + w10 * __ldg(Ub + r1 + x0) + w11 * __ldg(Ub + r1 + x1);
    wacc += us * ssum;
  }
  __shared__ float wp[4];
  if (lane == 0) wp[wid] = wacc;
  __syncthreads();
  if (threadIdx.x == 0)
    g_resacc[slice * (B_SZ * M16) + bm] = wp[0] + wp[1] + wp[2] + wp[3];
}

// ---------------------------------------------------------------------------
// Kernel: LM update.  grid = B blocks x 144 threads.
// ---------------------------------------------------------------------------
__global__ void update_kernel(unsigned k0, unsigned k1, float damping)
{
  int b = blockIdx.x;
  int m = threadIdx.x;
  if (m >= M_HYP) return;
  float res = 0.0f;
  if (m < M16) {
    float s = 0.0f;
#pragma unroll
    for (int p = 0; p < PS; p++) s += g_resacc[p * (B_SZ * M16) + b * M16 + m];
    res = s / (float)N_PTS;
  }
  g_costs[b * M_HYP + m] = res;

  float xi[6];
  unsigned base = (unsigned)((b * M_HYP + m) * 6);   // (8,144,6) flattened
  float s1 = -damping * res;
#pragma unroll
  for (int k = 0; k < 6; k++) {
    float nz = jax_normal_elem(k0, k1, base + (unsigned)k);
    xi[k] = s1 * nz * 0.01f;
  }
  float D[16];
  se3_exp6(xi, D);
  float* T = g_Tcur + (size_t)(b * M_HYP + m) * 16;
  float Told[16];
#pragma unroll
  for (int i = 0; i < 16; i++) Told[i] = T[i];
#pragma unroll
  for (int i = 0; i < 4; i++)
#pragma unroll
    for (int j = 0; j < 4; j++)
      T[i * 4 + j] = D[i * 4 + 0] * Told[0 * 4 + j] + D[i * 4 + 1] * Told[1 * 4 + j]
                   + D[i * 4 + 2] * Told[2 * 4 + j] + D[i * 4 + 3] * Told[3 * 4 + j];
}

// ---------------------------------------------------------------------------
// Kernel: geodesic + argmin + write output.  grid = B blocks x 144 threads.
// out[0:128]    = T_best (B,4,4)
// out[128:1280] = costs (B,144)
// ---------------------------------------------------------------------------
__global__ void final_kernel(const float* __restrict__ Tpred, float* __restrict__ out)
{
  int b = blockIdx.x;
  int m = threadIdx.x;
  __shared__ float tot[M_HYP];
  if (m < M_HYP) {
    const float* P = Tpred + b * 16;
    // rigid inverse of T_pred
    float Ri[9] = { P[0], P[4], P[8],  P[1], P[5], P[9],  P[2], P[6], P[10] };
    float tix = -(Ri[0] * P[3] + Ri[1] * P[7] + Ri[2] * P[11]);
    float tiy = -(Ri[3] * P[3] + Ri[4] * P[7] + Ri[5] * P[11]);
    float tiz = -(Ri[6] * P[3] + Ri[7] * P[7] + Ri[8] * P[11]);
    float Ti[16] = { Ri[0], Ri[1], Ri[2], tix,
                     Ri[3], Ri[4], Ri[5], tiy,
                     Ri[6], Ri[7], Ri[8], tiz,
                     0.f, 0.f, 0.f, 1.f };
    const float* Tc = g_Tcur + (size_t)(b * M_HYP + m) * 16;
    float A[16];
#pragma unroll
    for (int i = 0; i < 4; i++)
#pragma unroll
      for (int j = 0; j < 4; j++)
        A[i * 4 + j] = Tc[i * 4 + 0] * Ti[0 * 4 + j] + Tc[i * 4 + 1] * Ti[1 * 4 + j]
                     + Tc[i * 4 + 2] * Ti[2 * 4 + j] + Tc[i * 4 + 3] * Ti[3 * 4 + j];
    float cos_a = (A[0] + A[5] + A[10] - 1.0f) * 0.5f;
    const float CL = (float)(1.0 - 1e-7);
    cos_a = fminf(fmaxf(cos_a, -CL), CL);
    float theta = acosf(cos_a);
    float th = fmaxf(theta, 1e-8f);
    float sn = fmaxf(sinf(th), 1e-8f);
    float wx = (A[9] - A[6]) / (2.0f * sn) * th;
    float wy = (A[2] - A[8]) / (2.0f * sn) * th;
    float wz = (A[4] - A[1]) / (2.0f * sn) * th;
    if (fabsf(theta) < 1e-6f) { wx = 0.f; wy = 0.f; wz = 0.f; }
    float tx = A[3], ty = A[7], tz = A[11];
    float geod = sqrtf(tx * tx + ty * ty + tz * tz + wx * wx + wy * wy + wz * wz);
    float c = g_costs[b * M_HYP + m];
    tot[m] = c + geod;                       // MOTION_LAMBDA = 1
    out[128 + b * M_HYP + m] = c;
  }
  __syncthreads();
  if (m == 0) {
    int best = 0;
    float bv = tot[0];
    for (int i = 1; i < M_HYP; i++)
      if (tot[i] < bv) { bv = tot[i]; best = i; }
    const float* Tb = g_Tcur + (size_t)(b * M_HYP + best) * 16;
#pragma unroll
    for (int i = 0; i < 16; i++) out[b * 16 + i] = Tb[i];
  }
}

// ---------------------------------------------------------------------------
// Host launch
// ---------------------------------------------------------------------------
extern "C" void kernel_launch(void* const* d_in, const int* in_sizes, int n_in,
                              void* d_out, int out_size)
{
  const float* T_pred = (const float*)d_in[0];
  const float* geo    = (const float*)d_in[1];
  const float* Kin    = (const float*)d_in[2];
  const float* q0 = (const float*)d_in[3];
  const float* q1 = (const float*)d_in[4];
  const float* q2 = (const float*)d_in[5];
  const float* r0 = (const float*)d_in[6];
  const float* r1 = (const float*)d_in[7];
  const float* r2 = (const float*)d_in[8];
  const float* u0 = (const float*)d_in[9];
  const float* u1 = (const float*)d_in[10];
  const float* u2 = (const float*)d_in[11];
  float* out = (float*)d_out;

  float* D0p; float* D1p; float* D2p;
  cudaGetSymbolAddress((void**)&D0p, g_D0);
  cudaGetSymbolAddress((void**)&D1p, g_D1);
  cudaGetSymbolAddress((void**)&D2p, g_D2);

  // transposed diffs D = q - r  (channel-last)
  dim3 tb(32, 8);
  diff_transpose<<<dim3((H0 * W0) / 32, C0 / 32, B_SZ), tb>>>(q0, r0, D0p, C0, H0 * W0);
  diff_transpose<<<dim3((H1 * W1) / 32, C1 / 32, B_SZ), tb>>>(q1, r1, D1p, C1, H1 * W1);
  diff_transpose<<<dim3((H2 * W2) / 32, C2 / 32, B_SZ), tb>>>(q2, r2, D2p, C2, H2 * W2);

  // hypothesis key = fold_in(key(42), 0) = threefry((0,42),(0,0))
  unsigned hk0, hk1;
  threefry2x32(0u, 42u, 0u, 0u, &hk0, &hk1);
  hyp_kernel<<<1, M_HYP>>>(T_pred, hk0, hk1);

  const int   iters[3] = { 2, 3, 4 };
  const int   grid_res = B_SZ * M16 * PS;    // 1024 blocks
  for (int level = 0; level < 3; level++) {
    float scale = 1.0f / (4.0f / (float)(1 << level));
    float damping = (float)(0.001 * pow(0.5, (double)level));
    for (int it = 0; it < iters[level]; it++) {
      if (level == 0)
        residual_kernel<4><<<grid_res, 128>>>(D0p, u0, geo, Kin, C0, H0, W0, scale);
      else if (level == 1)
        residual_kernel<2><<<grid_res, 128>>>(D1p, u1, geo, Kin, C1, H1, W1, scale);
      else
        residual_kernel<1><<<grid_res, 128>>>(D2p, u2, geo, Kin, C2, H2, W2, scale);
      unsigned ik0, ik1;
      threefry2x32(0u, 42u, 0u, (unsigned)(100 + level * 10 + it), &ik0, &ik1);
      update_kernel<<<B_SZ, M_HYP>>>(ik0, ik1, damping);
    }
  }

  final_kernel<<<B_SZ, M_HYP>>>(T_pred, out);
  (void)in_sizes; (void)n_in; (void)out_size;
}

// round 5
// speedup vs baseline: 1.2598x; 1.2598x over previous
#include <cuda_runtime.h>
#include <cuda_bf16.h>
#include <math.h>

// ---------------------------------------------------------------------------
// Problem dimensions (fixed by the reference setup)
// ---------------------------------------------------------------------------
#define B_SZ   8
#define N_PTS  500
#define M_HYP  144
#define M16    16
#define PS     8           // point slices per (b,m) for the residual kernel

#define C0 128
#define H0 48
#define W0 64
#define C1 64
#define H1 96
#define W1 128
#define C2 32
#define H2 192
#define W2 256

// ---------------------------------------------------------------------------
// Scratch (__device__ globals — no allocation allowed). D stored as bf16.
// ---------------------------------------------------------------------------
__device__ __nv_bfloat16 g_D0[(size_t)B_SZ * H0 * W0 * C0];   // q0-r0, channel-last
__device__ __nv_bfloat16 g_D1[(size_t)B_SZ * H1 * W1 * C1];
__device__ __nv_bfloat16 g_D2[(size_t)B_SZ * H2 * W2 * C2];
__device__ float g_Tcur[B_SZ * M_HYP * 16];
__device__ float g_resacc[PS * B_SZ * M16];
__device__ float g_costs[B_SZ * M_HYP];

// ---------------------------------------------------------------------------
// Threefry-2x32 (exactly JAX's 20-round schedule; KAT-verified)
// ---------------------------------------------------------------------------
__host__ __device__ __forceinline__ void threefry2x32(
    unsigned k0, unsigned k1, unsigned x0, unsigned x1,
    unsigned* o0, unsigned* o1)
{
  unsigned ks2 = k0 ^ k1 ^ 0x1BD11BDAu;
#define TFR(r) { x0 += x1; x1 = (x1 << (r)) | (x1 >> (32 - (r))); x1 ^= x0; }
  x0 += k0;  x1 += k1;
  TFR(13) TFR(15) TFR(26) TFR(6)
  x0 += k1;  x1 += ks2 + 1u;
  TFR(17) TFR(29) TFR(16) TFR(24)
  x0 += ks2; x1 += k0 + 2u;
  TFR(13) TFR(15) TFR(26) TFR(6)
  x0 += k0;  x1 += k1 + 3u;
  TFR(17) TFR(29) TFR(16) TFR(24)
  x0 += k1;  x1 += ks2 + 4u;
  TFR(13) TFR(15) TFR(26) TFR(6)
  x0 += ks2; x1 += k0 + 5u;
#undef TFR
  *o0 = x0; *o1 = x1;
}

// Giles/XLA erfinv (same coefficients as XLA ErfInv32)
__device__ __forceinline__ float erfinv_f(float x)
{
  float w = -log1pf(-x * x);
  float p;
  if (w < 5.0f) {
    w = w - 2.5f;
    p = 2.81022636e-08f;
    p = fmaf(p, w, 3.43273939e-07f);
    p = fmaf(p, w, -3.5233877e-06f);
    p = fmaf(p, w, -4.39150654e-06f);
    p = fmaf(p, w, 0.00021858087f);
    p = fmaf(p, w, -0.00125372503f);
    p = fmaf(p, w, -0.00417768164f);
    p = fmaf(p, w, 0.246640727f);
    p = fmaf(p, w, 1.50140941f);
  } else {
    w = sqrtf(w) - 3.0f;
    p = -0.000200214257f;
    p = fmaf(p, w, 0.000100950558f);
    p = fmaf(p, w, 0.00134934322f);
    p = fmaf(p, w, -0.00367342844f);
    p = fmaf(p, w, 0.00573950773f);
    p = fmaf(p, w, -0.0076224613f);
    p = fmaf(p, w, 0.00943887047f);
    p = fmaf(p, w, 1.00167406f);
    p = fmaf(p, w, 2.83297682f);
  }
  return p * x;
}

__device__ __forceinline__ float bits_to_normal(unsigned bits)
{
  float u = __uint_as_float((bits >> 9) | 0x3f800000u) - 1.0f;
  const float lo = -0.99999994f;
  float v = fmaxf(lo, u * 2.0f + lo);
  return 1.41421356237f * erfinv_f(v);
}

// PARTITIONABLE threefry: (y0,y1) = threefry(key; 0, j); 32-bit draw = y0 ^ y1.
__device__ __forceinline__ float jax_normal_elem(unsigned k0, unsigned k1, unsigned j)
{
  unsigned y0, y1;
  threefry2x32(k0, k1, 0u, j, &y0, &y1);
  return bits_to_normal(y0 ^ y1);
}

// ---------------------------------------------------------------------------
// se3_exp (matches reference element-by-element)
// ---------------------------------------------------------------------------
__device__ __forceinline__ void mat3mul(const float* A, const float* Bm, float* Cm)
{
#pragma unroll
  for (int i = 0; i < 3; i++)
#pragma unroll
    for (int j = 0; j < 3; j++)
      Cm[i * 3 + j] = A[i * 3 + 0] * Bm[0 * 3 + j] + A[i * 3 + 1] * Bm[1 * 3 + j] + A[i * 3 + 2] * Bm[2 * 3 + j];
}

__device__ void se3_exp6(const float xi[6], float T[16])
{
  float tx = xi[0], ty = xi[1], tz = xi[2];
  float wx = xi[3], wy = xi[4], wz = xi[5];
  float theta = fmaxf(sqrtf(wx * wx + wy * wy + wz * wz), 1e-8f);
  float kx = wx / theta, ky = wy / theta, kz = wz / theta;
  float K[9] = { 0.f, -kz, ky,  kz, 0.f, -kx,  -ky, kx, 0.f };
  float KK[9];
  mat3mul(K, K, KK);
  float st = sinf(theta);
  float ct = 1.0f - cosf(theta);
  float a  = ct / theta;
  float bb = 1.0f - st / theta;
  float R[9], V[9];
#pragma unroll
  for (int i = 0; i < 9; i++) {
    float e = (i == 0 || i == 4 || i == 8) ? 1.0f : 0.0f;
    R[i] = e + st * K[i] + ct * KK[i];
    V[i] = e + a  * K[i] + bb * KK[i];
  }
  float tox = V[0] * tx + V[1] * ty + V[2] * tz;
  float toy = V[3] * tx + V[4] * ty + V[5] * tz;
  float toz = V[6] * tx + V[7] * ty + V[8] * tz;
  T[0] = R[0]; T[1] = R[1]; T[2]  = R[2]; T[3]  = tox;
  T[4] = R[3]; T[5] = R[4]; T[6]  = R[5]; T[7]  = toy;
  T[8] = R[6]; T[9] = R[7]; T[10] = R[8]; T[11] = toz;
  T[12] = 0.f; T[13] = 0.f; T[14] = 0.f; T[15] = 1.f;
}

// ---------------------------------------------------------------------------
// Kernel: D = q - r, transposed (B,C,HW) -> (B,HW,C), bf16 output
// ---------------------------------------------------------------------------
__global__ __launch_bounds__(256) void diff_transpose(
    const float* __restrict__ q, const float* __restrict__ r,
    __nv_bfloat16* __restrict__ Dt, int C, int HW)
{
  __shared__ float tile[32][33];
  int b   = blockIdx.z;
  int hw0 = blockIdx.x * 32;
  int c0  = blockIdx.y * 32;
  const float* qb = q + (size_t)b * C * HW;
  const float* rb = r + (size_t)b * C * HW;
  __nv_bfloat16* Db = Dt + (size_t)b * HW * C;
  int tx = threadIdx.x, ty = threadIdx.y;
#pragma unroll
  for (int i = ty; i < 32; i += 8) {
    int c = c0 + i, hw = hw0 + tx;
    tile[i][tx] = qb[(size_t)c * HW + hw] - rb[(size_t)c * HW + hw];
  }
  __syncthreads();
  int tid = ty * 32 + tx;
#pragma unroll
  for (int idx = tid; idx < 32 * 16; idx += 256) {
    int row = idx >> 4;         // local hw
    int pr  = idx & 15;         // channel pair
    __nv_bfloat162 h = __floats2bfloat162_rn(tile[2 * pr][row], tile[2 * pr + 1][row]);
    *(__nv_bfloat162*)(Db + (size_t)(hw0 + row) * C + c0 + 2 * pr) = h;
  }
}

// ---------------------------------------------------------------------------
// Kernel: hypotheses. grid = B_SZ blocks x 144 threads (dT redundant per block)
// ---------------------------------------------------------------------------
__global__ void hyp_kernel(const float* __restrict__ Tpred, unsigned k0, unsigned k1)
{
  int m = threadIdx.x;
  int b = blockIdx.x;
  if (m >= M_HYP) return;
  float xi[6];
#pragma unroll
  for (int k = 0; k < 3; k++)
    xi[k] = jax_normal_elem(k0, k1, (unsigned)(m * 3 + k));
  int pi = m / 12, yj = m % 12;
  const float D2R = (float)(3.14159265358979323846 / 180.0);
  xi[3] = 0.0f;
  xi[4] = (-11.0f + 2.0f * (float)pi) * D2R;
  xi[5] = (-11.0f + 2.0f * (float)yj) * D2R;
  float dT[16];
  se3_exp6(xi, dT);
  const float* P = Tpred + b * 16;
  float* O = g_Tcur + (size_t)(b * M_HYP + m) * 16;
#pragma unroll
  for (int i = 0; i < 4; i++)
#pragma unroll
    for (int j = 0; j < 4; j++)
      O[i * 4 + j] = dT[i * 4 + 0] * P[0 * 4 + j] + dT[i * 4 + 1] * P[1 * 4 + j]
                   + dT[i * 4 + 2] * P[2 * 4 + j] + dT[i * 4 + 3] * P[3 * 4 + j];
}

// ---------------------------------------------------------------------------
// Residuals.  grid = B*16*PS blocks, 256 threads (8 warps).
// Warp handles points n = 63*slice + wid, step 8. Lanes cover channels.
// CPL = channels per lane (bf16): 4 (C=128), 2 (C=64), 1 (C=32).
// Cross-lane reduction deferred to the end (us is lane-uniform).
// ---------------------------------------------------------------------------
template <int CPL>
__global__ __launch_bounds__(256) void residual_kernel(
    const __nv_bfloat16* __restrict__ Dt, const float* __restrict__ Umap,
    const float* __restrict__ geo, const float* __restrict__ Kin,
    int C, int H, int W, float scale)
{
  int bm    = blockIdx.x >> 3;     // / PS
  int slice = blockIdx.x & 7;
  int b = bm >> 4, m = bm & 15;
  int lane = threadIdx.x & 31, wid = threadIdx.x >> 5;

  const float* T = g_Tcur + (size_t)(b * M_HYP + m) * 16;
  float T00 = T[0], T01 = T[1], T02 = T[2],  T03 = T[3];
  float T10 = T[4], T11 = T[5], T12 = T[6],  T13 = T[7];
  float T20 = T[8], T21 = T[9], T22 = T[10], T23 = T[11];
  float fx = __ldg(Kin + b * 9 + 0) * scale, cx = __ldg(Kin + b * 9 + 2) * scale;
  float fy = __ldg(Kin + b * 9 + 4) * scale, cy = __ldg(Kin + b * 9 + 5) * scale;
  const __nv_bfloat16* Db = Dt + (size_t)b * H * W * C;
  const float* Ub = Umap + (size_t)b * H * W;
  const float* G  = geo + (size_t)b * N_PTS * 3;

  float Wm1 = (float)(W - 1), Hm1 = (float)(H - 1);
  float wacc = 0.0f;                       // per-lane accumulator
  int nbeg = slice * 63 + wid;
  int nend = min(N_PTS, slice * 63 + 63);
  for (int n = nbeg; n < nend; n += 8) {
    float X = __ldg(G + n * 3 + 0);
    float Y = __ldg(G + n * 3 + 1);
    float Z = __ldg(G + n * 3 + 2);
    float px = T00 * X + T01 * Y + T02 * Z + T03;
    float py = T10 * X + T11 * Y + T12 * Z + T13;
    float pz = T20 * X + T21 * Y + T22 * Z + T23;
    float z  = fmaxf(pz, 1e-6f);
    float u  = fx * (px / z) + cx;
    float v  = fy * (py / z) + cy;
    float gx = 2.0f * u / Wm1 - 1.0f;
    float gy = 2.0f * v / Hm1 - 1.0f;
    float xs = fminf(fmaxf(((gx + 1.0f) * (float)W - 1.0f) * 0.5f, 0.0f), Wm1);
    float ys = fminf(fmaxf(((gy + 1.0f) * (float)H - 1.0f) * 0.5f, 0.0f), Hm1);
    float x0f = floorf(xs), y0f = floorf(ys);
    float x1f = fminf(x0f + 1.0f, Wm1), y1f = fminf(y0f + 1.0f, Hm1);
    float wx = xs - x0f, wy = ys - y0f;
    int x0 = (int)x0f, x1 = (int)x1f, y0 = (int)y0f, y1 = (int)y1f;
    float w00 = (1.0f - wx) * (1.0f - wy), w01 = wx * (1.0f - wy);
    float w10 = (1.0f - wx) * wy,          w11 = wx * wy;
    int r0 = y0 * W, r1 = y1 * W;

    float us = w00 * __ldg(Ub + r0 + x0) + w01 * __ldg(Ub + r0 + x1)
             + w10 * __ldg(Ub + r1 + x0) + w11 * __ldg(Ub + r1 + x1);

    float ssum = 0.0f;
    if constexpr (CPL == 4) {
      uint2 va = __ldg((const uint2*)(Db + (size_t)(r0 + x0) * C) + lane);
      uint2 vb = __ldg((const uint2*)(Db + (size_t)(r0 + x1) * C) + lane);
      uint2 vc = __ldg((const uint2*)(Db + (size_t)(r1 + x0) * C) + lane);
      uint2 vd = __ldg((const uint2*)(Db + (size_t)(r1 + x1) * C) + lane);
      float2 a0 = __bfloat1622float2(*(__nv_bfloat162*)&va.x);
      float2 a1 = __bfloat1622float2(*(__nv_bfloat162*)&va.y);
      float2 b0 = __bfloat1622float2(*(__nv_bfloat162*)&vb.x);
      float2 b1 = __bfloat1622float2(*(__nv_bfloat162*)&vb.y);
      float2 c0v = __bfloat1622float2(*(__nv_bfloat162*)&vc.x);
      float2 c1 = __bfloat1622float2(*(__nv_bfloat162*)&vc.y);
      float2 d0v = __bfloat1622float2(*(__nv_bfloat162*)&vd.x);
      float2 d1 = __bfloat1622float2(*(__nv_bfloat162*)&vd.y);
      float e0 = w00 * a0.x + w01 * b0.x + w10 * c0v.x + w11 * d0v.x;
      float e1 = w00 * a0.y + w01 * b0.y + w10 * c0v.y + w11 * d0v.y;
      float e2 = w00 * a1.x + w01 * b1.x + w10 * c1.x + w11 * d1.x;
      float e3 = w00 * a1.y + w01 * b1.y + w10 * c1.y + w11 * d1.y;
      ssum = e0 * e0 + e1 * e1 + e2 * e2 + e3 * e3;
    } else if constexpr (CPL == 2) {
      unsigned va = __ldg((const unsigned*)(Db + (size_t)(r0 + x0) * C) + lane);
      unsigned vb = __ldg((const unsigned*)(Db + (size_t)(r0 + x1) * C) + lane);
      unsigned vc = __ldg((const unsigned*)(Db + (size_t)(r1 + x0) * C) + lane);
      unsigned vd = __ldg((const unsigned*)(Db + (size_t)(r1 + x1) * C) + lane);
      float2 a = __bfloat1622float2(*(__nv_bfloat162*)&va);
      float2 bq = __bfloat1622float2(*(__nv_bfloat162*)&vb);
      float2 c = __bfloat1622float2(*(__nv_bfloat162*)&vc);
      float2 d = __bfloat1622float2(*(__nv_bfloat162*)&vd);
      float e0 = w00 * a.x + w01 * bq.x + w10 * c.x + w11 * d.x;
      float e1 = w00 * a.y + w01 * bq.y + w10 * c.y + w11 * d.y;
      ssum = e0 * e0 + e1 * e1;
    } else {
      float a  = __bfloat162float(__ldg(Db + (size_t)(r0 + x0) * C + lane));
      float bq = __bfloat162float(__ldg(Db + (size_t)(r0 + x1) * C + lane));
      float c  = __bfloat162float(__ldg(Db + (size_t)(r1 + x0) * C + lane));
      float d  = __bfloat162float(__ldg(Db + (size_t)(r1 + x1) * C + lane));
      float e0 = w00 * a + w01 * bq + w10 * c + w11 * d;
      ssum = e0 * e0;
    }
    wacc += us * ssum;     // deferred cross-lane reduction
  }
  // one butterfly at the end
#pragma unroll
  for (int o = 16; o; o >>= 1) wacc += __shfl_xor_sync(0xffffffffu, wacc, o);
  __shared__ float wp[8];
  if (lane == 0) wp[wid] = wacc;
  __syncthreads();
  if (threadIdx.x == 0) {
    float s = 0.0f;
#pragma unroll
    for (int w = 0; w < 8; w++) s += wp[w];
    g_resacc[slice * (B_SZ * M16) + bm] = s;
  }
}

// ---------------------------------------------------------------------------
// Kernel: LM update.  grid = B blocks x 144 threads.
// ---------------------------------------------------------------------------
__global__ void update_kernel(unsigned k0, unsigned k1, float damping)
{
  int b = blockIdx.x;
  int m = threadIdx.x;
  if (m >= M_HYP) return;
  float res = 0.0f;
  if (m < M16) {
    float s = 0.0f;
#pragma unroll
    for (int p = 0; p < PS; p++) s += g_resacc[p * (B_SZ * M16) + b * M16 + m];
    res = s / (float)N_PTS;
  }
  g_costs[b * M_HYP + m] = res;

  float xi[6];
  unsigned base = (unsigned)((b * M_HYP + m) * 6);
  float s1 = -damping * res;
#pragma unroll
  for (int k = 0; k < 6; k++) {
    float nz = jax_normal_elem(k0, k1, base + (unsigned)k);
    xi[k] = s1 * nz * 0.01f;
  }
  float D[16];
  se3_exp6(xi, D);
  float* T = g_Tcur + (size_t)(b * M_HYP + m) * 16;
  float Told[16];
#pragma unroll
  for (int i = 0; i < 16; i++) Told[i] = T[i];
#pragma unroll
  for (int i = 0; i < 4; i++)
#pragma unroll
    for (int j = 0; j < 4; j++)
      T[i * 4 + j] = D[i * 4 + 0] * Told[0 * 4 + j] + D[i * 4 + 1] * Told[1 * 4 + j]
                   + D[i * 4 + 2] * Told[2 * 4 + j] + D[i * 4 + 3] * Told[3 * 4 + j];
}

// ---------------------------------------------------------------------------
// Kernel: geodesic + argmin + output.  grid = B blocks x 144 threads.
// ---------------------------------------------------------------------------
__global__ void final_kernel(const float* __restrict__ Tpred, float* __restrict__ out)
{
  int b = blockIdx.x;
  int m = threadIdx.x;
  __shared__ float tot[M_HYP];
  if (m < M_HYP) {
    const float* P = Tpred + b * 16;
    float Ri[9] = { P[0], P[4], P[8],  P[1], P[5], P[9],  P[2], P[6], P[10] };
    float tix = -(Ri[0] * P[3] + Ri[1] * P[7] + Ri[2] * P[11]);
    float tiy = -(Ri[3] * P[3] + Ri[4] * P[7] + Ri[5] * P[11]);
    float tiz = -(Ri[6] * P[3] + Ri[7] * P[7] + Ri[8] * P[11]);
    float Ti[16] = { Ri[0], Ri[1], Ri[2], tix,
                     Ri[3], Ri[4], Ri[5], tiy,
                     Ri[6], Ri[7], Ri[8], tiz,
                     0.f, 0.f, 0.f, 1.f };
    const float* Tc = g_Tcur + (size_t)(b * M_HYP + m) * 16;
    float A[16];
#pragma unroll
    for (int i = 0; i < 4; i++)
#pragma unroll
      for (int j = 0; j < 4; j++)
        A[i * 4 + j] = Tc[i * 4 + 0] * Ti[0 * 4 + j] + Tc[i * 4 + 1] * Ti[1 * 4 + j]
                     + Tc[i * 4 + 2] * Ti[2 * 4 + j] + Tc[i * 4 + 3] * Ti[3 * 4 + j];
    float cos_a = (A[0] + A[5] + A[10] - 1.0f) * 0.5f;
    const float CL = (float)(1.0 - 1e-7);
    cos_a = fminf(fmaxf(cos_a, -CL), CL);
    float theta = acosf(cos_a);
    float th = fmaxf(theta, 1e-8f);
    float sn = fmaxf(sinf(th), 1e-8f);
    float wx = (A[9] - A[6]) / (2.0f * sn) * th;
    float wy = (A[2] - A[8]) / (2.0f * sn) * th;
    float wz = (A[4] - A[1]) / (2.0f * sn) * th;
    if (fabsf(theta) < 1e-6f) { wx = 0.f; wy = 0.f; wz = 0.f; }
    float tx = A[3], ty = A[7], tz = A[11];
    float geod = sqrtf(tx * tx + ty * ty + tz * tz + wx * wx + wy * wy + wz * wz);
    float c = g_costs[b * M_HYP + m];
    tot[m] = c + geod;
    out[128 + b * M_HYP + m] = c;
  }
  __syncthreads();
  if (m == 0) {
    int best = 0;
    float bv = tot[0];
    for (int i = 1; i < M_HYP; i++)
      if (tot[i] < bv) { bv = tot[i]; best = i; }
    const float* Tb = g_Tcur + (size_t)(b * M_HYP + best) * 16;
#pragma unroll
    for (int i = 0; i < 16; i++) out[b * 16 + i] = Tb[i];
  }
}

// ---------------------------------------------------------------------------
// Host launch
// ---------------------------------------------------------------------------
extern "C" void kernel_launch(void* const* d_in, const int* in_sizes, int n_in,
                              void* d_out, int out_size)
{
  const float* T_pred = (const float*)d_in[0];
  const float* geo    = (const float*)d_in[1];
  const float* Kin    = (const float*)d_in[2];
  const float* q0 = (const float*)d_in[3];
  const float* q1 = (const float*)d_in[4];
  const float* q2 = (const float*)d_in[5];
  const float* r0 = (const float*)d_in[6];
  const float* r1 = (const float*)d_in[7];
  const float* r2 = (const float*)d_in[8];
  const float* u0 = (const float*)d_in[9];
  const float* u1 = (const float*)d_in[10];
  const float* u2 = (const float*)d_in[11];
  float* out = (float*)d_out;

  __nv_bfloat16 *D0p, *D1p, *D2p;
  cudaGetSymbolAddress((void**)&D0p, g_D0);
  cudaGetSymbolAddress((void**)&D1p, g_D1);
  cudaGetSymbolAddress((void**)&D2p, g_D2);

  // transposed diffs D = q - r  (channel-last, bf16)
  dim3 tb(32, 8);
  diff_transpose<<<dim3((H0 * W0) / 32, C0 / 32, B_SZ), tb>>>(q0, r0, D0p, C0, H0 * W0);
  diff_transpose<<<dim3((H1 * W1) / 32, C1 / 32, B_SZ), tb>>>(q1, r1, D1p, C1, H1 * W1);
  diff_transpose<<<dim3((H2 * W2) / 32, C2 / 32, B_SZ), tb>>>(q2, r2, D2p, C2, H2 * W2);

  unsigned hk0, hk1;
  threefry2x32(0u, 42u, 0u, 0u, &hk0, &hk1);
  hyp_kernel<<<B_SZ, M_HYP>>>(T_pred, hk0, hk1);

  const int iters[3] = { 2, 3, 4 };
  const int grid_res = B_SZ * M16 * PS;    // 1024 blocks
  for (int level = 0; level < 3; level++) {
    float scale = 1.0f / (4.0f / (float)(1 << level));
    float damping = (float)(0.001 * pow(0.5, (double)level));
    for (int it = 0; it < iters[level]; it++) {
      if (level == 0)
        residual_kernel<4><<<grid_res, 256>>>(D0p, u0, geo, Kin, C0, H0, W0, scale);
      else if (level == 1)
        residual_kernel<2><<<grid_res, 256>>>(D1p, u1, geo, Kin, C1, H1, W1, scale);
      else
        residual_kernel<1><<<grid_res, 256>>>(D2p, u2, geo, Kin, C2, H2, W2, scale);
      unsigned ik0, ik1;
      threefry2x32(0u, 42u, 0u, (unsigned)(100 + level * 10 + it), &ik0, &ik1);
      update_kernel<<<B_SZ, M_HYP>>>(ik0, ik1, damping);
    }
  }

  final_kernel<<<B_SZ, M_HYP>>>(T_pred, out);
  (void)in_sizes; (void)n_in; (void)out_size;
}